// round 12
// baseline (speedup 1.0000x reference)
#include <cuda_runtime.h>
#include <cuda_bf16.h>
#include <cuda_fp16.h>
#include <cstdint>

// Problem constants
#define NROW 16384
#define DIMK 128
#define NTILE 128          // NROW / 128 tiles per dimension
#define NTILES (NTILE * NTILE)
#define GRID_PERSIST 296   // 2 CTAs per SM on 148 SMs

// log2(e) * 5  (exp(x/T) = 2^(x*5*log2e), T = 0.2) — folded into v1 at prep.
#define K_EXP2 7.2134752044448170f

// Scratch (static device globals — no runtime allocation)
static __device__ __align__(16) __nv_bfloat16 g_v1[NROW * DIMK];  // pre-scaled by K_EXP2
static __device__ __align__(16) __nv_bfloat16 g_v2[NROW * DIMK];
static __device__ float g_rowsum[NROW];
static __device__ float g_diag_part[NROW / 4];

__device__ __forceinline__ uint32_t smem_u32(const void* p) {
    uint32_t a;
    asm("{ .reg .u64 t; cvta.to.shared.u64 t, %1; cvt.u32.u64 %0, t; }"
        : "=r"(a) : "l"(p));
    return a;
}

__device__ __forceinline__ void cp_async16(uint32_t smem_dst, const void* gsrc) {
    asm volatile("cp.async.cg.shared.global [%0], [%1], 16;"
                 :: "r"(smem_dst), "l"(gsrc) : "memory");
}

__device__ __forceinline__ void ldsm4(uint32_t* r, uint32_t addr) {
    asm volatile("ldmatrix.sync.aligned.m8n8.x4.shared.b16 {%0,%1,%2,%3}, [%4];"
                 : "=r"(r[0]), "=r"(r[1]), "=r"(r[2]), "=r"(r[3]) : "r"(addr));
}

__device__ __forceinline__ void mma16816(float* d, const uint32_t* a, const uint32_t* b) {
    asm volatile(
        "mma.sync.aligned.m16n8k16.row.col.f32.bf16.bf16.f32 "
        "{%0,%1,%2,%3}, {%4,%5,%6,%7}, {%8,%9}, {%0,%1,%2,%3};"
        : "+f"(d[0]), "+f"(d[1]), "+f"(d[2]), "+f"(d[3])
        : "r"(a[0]), "r"(a[1]), "r"(a[2]), "r"(a[3]), "r"(b[0]), "r"(b[1]));
}

// ---------------------------------------------------------------------------
// Kernel 1: normalize rows (fp32), emit bf16 copies (v1 pre-scaled by K_EXP2),
// per-block diag partials (fp32-exact), and zero g_rowsum.
// One warp per row; 4 warps per block.
// ---------------------------------------------------------------------------
__global__ void __launch_bounds__(128) cl_prep(const float* __restrict__ emb) {
    __shared__ float sh_diag[4];
    int wid = threadIdx.x >> 5, lane = threadIdx.x & 31;
    int row = blockIdx.x * 4 + wid;

    const float4* r0 = (const float4*)(emb) + (size_t)row * (DIMK / 4) + lane;
    const float4* r1 = (const float4*)(emb + (size_t)NROW * DIMK) + (size_t)row * (DIMK / 4) + lane;
    float4 a = *r0;
    float4 b = *r1;

    float s00 = a.x * a.x + a.y * a.y + a.z * a.z + a.w * a.w;
    float s11 = b.x * b.x + b.y * b.y + b.z * b.z + b.w * b.w;
    float s01 = a.x * b.x + a.y * b.y + a.z * b.z + a.w * b.w;
#pragma unroll
    for (int m = 16; m; m >>= 1) {
        s00 += __shfl_xor_sync(0xffffffffu, s00, m);
        s11 += __shfl_xor_sync(0xffffffffu, s11, m);
        s01 += __shfl_xor_sync(0xffffffffu, s01, m);
    }
    // matches F.normalize: x / max(||x||, eps)
    float inv0 = 1.0f / fmaxf(sqrtf(s00), 1e-12f);
    float inv1 = 1.0f / fmaxf(sqrtf(s11), 1e-12f);
    float inv0s = inv0 * K_EXP2;   // fold exp scale into v1

    __nv_bfloat162* o1 = (__nv_bfloat162*)g_v1 + (size_t)row * (DIMK / 2) + lane * 2;
    __nv_bfloat162* o2 = (__nv_bfloat162*)g_v2 + (size_t)row * (DIMK / 2) + lane * 2;
    o1[0] = __floats2bfloat162_rn(a.x * inv0s, a.y * inv0s);
    o1[1] = __floats2bfloat162_rn(a.z * inv0s, a.w * inv0s);
    o2[0] = __floats2bfloat162_rn(b.x * inv1, b.y * inv1);
    o2[1] = __floats2bfloat162_rn(b.z * inv1, b.w * inv1);

    if (lane == 0) {
        g_rowsum[row] = 0.0f;
        sh_diag[wid] = s01 * inv0 * inv1;   // exact fp32 diagonal (unscaled)
    }
    __syncthreads();
    if (threadIdx.x == 0)
        g_diag_part[blockIdx.x] = sh_diag[0] + sh_diag[1] + sh_diag[2] + sh_diag[3];
}

// issue one tile's A+B loads (swizzled cp.async) and commit the group
__device__ __forceinline__ void issue_tile_loads(
    uint32_t sA, uint32_t sB, int t, int tid)
{
    const uint4* asrc = (const uint4*)(g_v1 + (size_t)(t >> 7) * 128 * DIMK);
    const uint4* bsrc = (const uint4*)(g_v2 + (size_t)(t & 127) * 128 * DIMK);
#pragma unroll
    for (int it = 0; it < 8; it++) {
        int ci = tid + it * 256;
        int row = ci >> 4, c = ci & 15;
        uint32_t off = (uint32_t)row * 256u + (uint32_t)((c ^ (row & 7)) << 4);
        cp_async16(sA + off, asrc + ci);
        cp_async16(sB + off, bsrc + ci);
    }
    asm volatile("cp.async.commit_group;" ::: "memory");
}

// ---------------------------------------------------------------------------
// Kernel 2: persistent fused GEMM + exp + per-row sums.
// Grid = 296 CTAs (2/SM); each loops tiles t = bid, bid+296, ...
// Per tile: wait loads -> pipelined bf16 HMMA mainloop (R10) -> sync ->
// issue NEXT tile's cp.async -> f16x2 exp epilogue (MUFU hides the load).
// 8 warps in 4(m) x 2(n) grid; warp tile 32x64 = 2x8 m16n8k16 tiles.
// SMEM: [128][128] bf16 per matrix, 16B chunks XOR-swizzled c' = c^(row&7).
// ---------------------------------------------------------------------------
__global__ void __launch_bounds__(256, 2) cl_gemm() {
    extern __shared__ __align__(1024) char smem[];
    const uint32_t sA = smem_u32(smem);
    const uint32_t sB = sA + 32768u;

    int tid = threadIdx.x, wid = tid >> 5, lane = tid & 31;

    int wm = wid & 3;        // warp row in 4x2 grid
    int wn = wid >> 2;       // warp col
    int row_base = wm * 32;
    int col_base = wn * 64;

    int lr = lane & 7;
    int q  = lane >> 3;

    // A fragment rows: lanes 0-7 rows 0-7, 8-15 rows 8-15 (k lo),
    // 16-23 rows 0-7, 24-31 rows 8-15 (k hi)
    int arow0 = row_base + (q & 1) * 8 + lr;         // mt = 0
    int arow1 = arow0 + 16;                          // mt = 1
    int aqk   = q >> 1;
    // B fragment rows: lanes 0-15 n 0-7 (k lo/hi), 16-31 n 8-15
    int brow_r = col_base + (q >> 1) * 8 + lr;
    int bqk   = q & 1;

    const uint32_t aBase0 = sA + (uint32_t)arow0 * 256u;
    const uint32_t aBase1 = sA + (uint32_t)arow1 * 256u;
    const uint32_t aSw0 = (uint32_t)(arow0 & 7);
    const uint32_t aSw1 = (uint32_t)(arow1 & 7);

    int t = blockIdx.x;
    issue_tile_loads(sA, sB, t, tid);

    while (t < NTILES) {
        int tn = t + GRID_PERSIST;

        asm volatile("cp.async.wait_group 0;" ::: "memory");
        __syncthreads();

        float acc[2][8][4];
#pragma unroll
        for (int mt = 0; mt < 2; mt++)
#pragma unroll
            for (int nt = 0; nt < 8; nt++)
#pragma unroll
                for (int k = 0; k < 4; k++) acc[mt][nt][k] = 0.0f;

        uint32_t aF[2][2][4];   // [buffer][mt][frag]
        {
            uint32_t kch = (uint32_t)aqk;
            ldsm4(aF[0][0], aBase0 + ((kch ^ aSw0) << 4));
            ldsm4(aF[0][1], aBase1 + ((kch ^ aSw1) << 4));
        }

#pragma unroll
        for (int s = 0; s < 8; s++) {
            const int cur = s & 1, nxt = cur ^ 1;
            uint32_t kchB = (uint32_t)(s * 2 + bqk);
            uint32_t b[4][4];

            {
                int nr0 = brow_r;
                int nr1 = brow_r + 16;
                ldsm4(b[0], sB + (uint32_t)nr0 * 256u + ((kchB ^ (uint32_t)(nr0 & 7)) << 4));
                ldsm4(b[1], sB + (uint32_t)nr1 * 256u + ((kchB ^ (uint32_t)(nr1 & 7)) << 4));
            }
            mma16816(acc[0][0], aF[cur][0], b[0]);
            mma16816(acc[1][0], aF[cur][1], b[0]);
            mma16816(acc[0][1], aF[cur][0], b[0] + 2);
            mma16816(acc[1][1], aF[cur][1], b[0] + 2);
            {
                int nr = brow_r + 32;
                ldsm4(b[2], sB + (uint32_t)nr * 256u + ((kchB ^ (uint32_t)(nr & 7)) << 4));
            }
            mma16816(acc[0][2], aF[cur][0], b[1]);
            mma16816(acc[1][2], aF[cur][1], b[1]);
            mma16816(acc[0][3], aF[cur][0], b[1] + 2);
            mma16816(acc[1][3], aF[cur][1], b[1] + 2);
            {
                int nr = brow_r + 48;
                ldsm4(b[3], sB + (uint32_t)nr * 256u + ((kchB ^ (uint32_t)(nr & 7)) << 4));
            }
            mma16816(acc[0][4], aF[cur][0], b[2]);
            mma16816(acc[1][4], aF[cur][1], b[2]);
            mma16816(acc[0][5], aF[cur][0], b[2] + 2);
            mma16816(acc[1][5], aF[cur][1], b[2] + 2);
            if (s < 7) {
                uint32_t kchA = (uint32_t)((s + 1) * 2 + aqk);
                ldsm4(aF[nxt][0], aBase0 + ((kchA ^ aSw0) << 4));
                ldsm4(aF[nxt][1], aBase1 + ((kchA ^ aSw1) << 4));
            }
            mma16816(acc[0][6], aF[cur][0], b[3]);
            mma16816(acc[1][6], aF[cur][1], b[3]);
            mma16816(acc[0][7], aF[cur][0], b[3] + 2);
            mma16816(acc[1][7], aF[cur][1], b[3] + 2);
        }

        // All smem reads for this tile are done -> start next tile's loads,
        // then do the MUFU epilogue while they stream in.
        __syncthreads();
        if (tn < NTILES) issue_tile_loads(sA, sB, tn, tid);

        // ---- epilogue: f16x2 exp (scale pre-folded into v1) + row sums ----
        // m16n8 accum layout: d0,d1 -> row (lane>>2), d2,d3 -> row (lane>>2)+8.
        int tile_m_row = (t >> 7) * 128 + row_base + (lane >> 2);
#pragma unroll
        for (int mt = 0; mt < 2; mt++) {
            __half2 h0 = __floats2half2_rn(0.0f, 0.0f);
            __half2 h1 = __floats2half2_rn(0.0f, 0.0f);
#pragma unroll
            for (int nt = 0; nt < 8; nt++) {
                h0 = __hadd2(h0, h2exp2(__floats2half2_rn(acc[mt][nt][0], acc[mt][nt][1])));
                h1 = __hadd2(h1, h2exp2(__floats2half2_rn(acc[mt][nt][2], acc[mt][nt][3])));
            }
            float s0 = __low2float(h0) + __high2float(h0);
            float s1 = __low2float(h1) + __high2float(h1);
            s0 += __shfl_xor_sync(0xffffffffu, s0, 1);
            s0 += __shfl_xor_sync(0xffffffffu, s0, 2);
            s1 += __shfl_xor_sync(0xffffffffu, s1, 1);
            s1 += __shfl_xor_sync(0xffffffffu, s1, 2);
            if ((lane & 3) == 0) {
                int gr = tile_m_row + mt * 16;
                atomicAdd(&g_rowsum[gr], s0);
                atomicAdd(&g_rowsum[gr + 8], s1);
            }
        }

        t = tn;
    }
}

// ---------------------------------------------------------------------------
// Kernel 3: loss = sum_i log(rowsum_i) - (sum diag partials)/T
// ---------------------------------------------------------------------------
__global__ void __launch_bounds__(1024) cl_finalize(float* __restrict__ out) {
    __shared__ float sh[1024];
    int tid = threadIdx.x;
    float s = 0.0f;
    for (int i = tid; i < NROW; i += 1024)
        s += __logf(g_rowsum[i]);
    for (int i = tid; i < NROW / 4; i += 1024)
        s -= 5.0f * g_diag_part[i];
    sh[tid] = s;
    __syncthreads();
    for (int d = 512; d > 0; d >>= 1) {
        if (tid < d) sh[tid] += sh[tid + d];
        __syncthreads();
    }
    if (tid == 0) out[0] = sh[0];
}

// ---------------------------------------------------------------------------
extern "C" void kernel_launch(void* const* d_in, const int* in_sizes, int n_in,
                              void* d_out, int out_size) {
    (void)in_sizes; (void)n_in; (void)out_size;
    const float* emb = (const float*)d_in[0];
    float* out = (float*)d_out;

    cudaFuncSetAttribute(cl_gemm, cudaFuncAttributeMaxDynamicSharedMemorySize,
                         65536);

    cl_prep<<<NROW / 4, 128>>>(emb);
    cl_gemm<<<GRID_PERSIST, 256, 65536>>>();
    cl_finalize<<<1, 1024>>>(out);
}

// round 13
// speedup vs baseline: 1.1792x; 1.1792x over previous
#include <cuda_runtime.h>
#include <cuda_bf16.h>
#include <cuda_fp16.h>
#include <cstdint>

// Problem constants
#define NROW 16384
#define DIMK 128

// log2(e) * 5  (exp(x/T) = 2^(x*5*log2e), T = 0.2) — folded into v1 at prep.
#define K_EXP2 7.2134752044448170f

// Scratch (static device globals — no runtime allocation)
static __device__ __align__(16) __nv_bfloat16 g_v1[NROW * DIMK];  // pre-scaled by K_EXP2
static __device__ __align__(16) __nv_bfloat16 g_v2[NROW * DIMK];
static __device__ float g_rowsum[NROW];
static __device__ float g_diag_part[NROW / 4];

__device__ __forceinline__ uint32_t smem_u32(const void* p) {
    uint32_t a;
    asm("{ .reg .u64 t; cvta.to.shared.u64 t, %1; cvt.u32.u64 %0, t; }"
        : "=r"(a) : "l"(p));
    return a;
}

__device__ __forceinline__ void cp_async16(uint32_t smem_dst, const void* gsrc) {
    asm volatile("cp.async.cg.shared.global [%0], [%1], 16;"
                 :: "r"(smem_dst), "l"(gsrc) : "memory");
}

__device__ __forceinline__ void ldsm4(uint32_t* r, uint32_t addr) {
    asm volatile("ldmatrix.sync.aligned.m8n8.x4.shared.b16 {%0,%1,%2,%3}, [%4];"
                 : "=r"(r[0]), "=r"(r[1]), "=r"(r[2]), "=r"(r[3]) : "r"(addr));
}

__device__ __forceinline__ void mma16816(float* d, const uint32_t* a, const uint32_t* b) {
    asm volatile(
        "mma.sync.aligned.m16n8k16.row.col.f32.bf16.bf16.f32 "
        "{%0,%1,%2,%3}, {%4,%5,%6,%7}, {%8,%9}, {%0,%1,%2,%3};"
        : "+f"(d[0]), "+f"(d[1]), "+f"(d[2]), "+f"(d[3])
        : "r"(a[0]), "r"(a[1]), "r"(a[2]), "r"(a[3]), "r"(b[0]), "r"(b[1]));
}

// pack two f32 into f16x2 (single SASS cvt), exp2 on the pair (single MUFU op)
__device__ __forceinline__ uint32_t cvt_f16x2(float lo, float hi) {
    uint32_t r;
    asm("cvt.rn.f16x2.f32 %0, %1, %2;" : "=r"(r) : "f"(hi), "f"(lo));
    return r;
}
__device__ __forceinline__ uint32_t ex2_f16x2(uint32_t x) {
    uint32_t r;
    asm("ex2.approx.f16x2 %0, %1;" : "=r"(r) : "r"(x));
    return r;
}

// ---------------------------------------------------------------------------
// Kernel 1: normalize rows (fp32), emit bf16 copies (v1 pre-scaled by K_EXP2),
// per-block diag partials (fp32-exact), zero g_rowsum, zero out[0].
// One warp per row; 4 warps per block.
// ---------------------------------------------------------------------------
__global__ void __launch_bounds__(128) cl_prep(const float* __restrict__ emb,
                                               float* __restrict__ out) {
    __shared__ float sh_diag[4];
    int wid = threadIdx.x >> 5, lane = threadIdx.x & 31;
    int row = blockIdx.x * 4 + wid;

    const float4* r0 = (const float4*)(emb) + (size_t)row * (DIMK / 4) + lane;
    const float4* r1 = (const float4*)(emb + (size_t)NROW * DIMK) + (size_t)row * (DIMK / 4) + lane;
    float4 a = *r0;
    float4 b = *r1;

    float s00 = a.x * a.x + a.y * a.y + a.z * a.z + a.w * a.w;
    float s11 = b.x * b.x + b.y * b.y + b.z * b.z + b.w * b.w;
    float s01 = a.x * b.x + a.y * b.y + a.z * b.z + a.w * b.w;
#pragma unroll
    for (int m = 16; m; m >>= 1) {
        s00 += __shfl_xor_sync(0xffffffffu, s00, m);
        s11 += __shfl_xor_sync(0xffffffffu, s11, m);
        s01 += __shfl_xor_sync(0xffffffffu, s01, m);
    }
    // matches F.normalize: x / max(||x||, eps)
    float inv0 = 1.0f / fmaxf(sqrtf(s00), 1e-12f);
    float inv1 = 1.0f / fmaxf(sqrtf(s11), 1e-12f);
    float inv0s = inv0 * K_EXP2;   // fold exp scale into v1

    __nv_bfloat162* o1 = (__nv_bfloat162*)g_v1 + (size_t)row * (DIMK / 2) + lane * 2;
    __nv_bfloat162* o2 = (__nv_bfloat162*)g_v2 + (size_t)row * (DIMK / 2) + lane * 2;
    o1[0] = __floats2bfloat162_rn(a.x * inv0s, a.y * inv0s);
    o1[1] = __floats2bfloat162_rn(a.z * inv0s, a.w * inv0s);
    o2[0] = __floats2bfloat162_rn(b.x * inv1, b.y * inv1);
    o2[1] = __floats2bfloat162_rn(b.z * inv1, b.w * inv1);

    if (lane == 0) {
        g_rowsum[row] = 0.0f;
        sh_diag[wid] = s01 * inv0 * inv1;   // exact fp32 diagonal (unscaled)
    }
    if (blockIdx.x == 0 && threadIdx.x == 0) out[0] = 0.0f;
    __syncthreads();
    if (threadIdx.x == 0)
        g_diag_part[blockIdx.x] = sh_diag[0] + sh_diag[1] + sh_diag[2] + sh_diag[3];
}

// ---------------------------------------------------------------------------
// Kernel 2: fused GEMM tile (mma.sync bf16 HMMA) + exp + per-row sums.
// CTA = 128x128 tile of (K_EXP2*sim) = (K_EXP2*v1) @ v2^T, K=128 in smem.
// 8 warps in 4(m) x 2(n) grid; warp tile 32x64 = 2x8 m16n8k16 tiles.
// SMEM: row-major [128][128] bf16, 16B chunks XOR-swizzled: c' = c ^ (row&7).
// Mainloop software-pipelined (R10). Epilogue uses packed f16x2 ex2 to halve
// MUFU issue. 2 CTAs/SM so load phases overlap the other CTA's compute.
// ---------------------------------------------------------------------------
__global__ void __launch_bounds__(256, 2) cl_gemm() {
    extern __shared__ __align__(1024) char smem[];
    const uint32_t sA = smem_u32(smem);
    const uint32_t sB = sA + 32768u;

    int tid = threadIdx.x, wid = tid >> 5, lane = tid & 31;
    int tile_n = blockIdx.x, tile_m = blockIdx.y;

    // ---- global -> smem via cp.async (swizzled), 8 x 16B per thread/tile ----
    const uint4* asrc = (const uint4*)(g_v1 + (size_t)tile_m * 128 * DIMK);
    const uint4* bsrc = (const uint4*)(g_v2 + (size_t)tile_n * 128 * DIMK);
#pragma unroll
    for (int it = 0; it < 8; it++) {
        int ci = tid + it * 256;
        int row = ci >> 4, c = ci & 15;
        uint32_t off = (uint32_t)row * 256u + (uint32_t)((c ^ (row & 7)) << 4);
        cp_async16(sA + off, asrc + ci);
        cp_async16(sB + off, bsrc + ci);
    }
    asm volatile("cp.async.commit_group;" ::: "memory");
    asm volatile("cp.async.wait_group 0;" ::: "memory");
    __syncthreads();

    int wm = wid & 3;        // warp row in 4x2 grid
    int wn = wid >> 2;       // warp col
    int row_base = wm * 32;
    int col_base = wn * 64;

    float acc[2][8][4];
#pragma unroll
    for (int mt = 0; mt < 2; mt++)
#pragma unroll
        for (int nt = 0; nt < 8; nt++)
#pragma unroll
            for (int k = 0; k < 4; k++) acc[mt][nt][k] = 0.0f;

    int lr = lane & 7;
    int q  = lane >> 3;

    // A fragment rows: lanes 0-7 rows 0-7, 8-15 rows 8-15 (k lo),
    // 16-23 rows 0-7, 24-31 rows 8-15 (k hi)
    int arow0 = row_base + (q & 1) * 8 + lr;         // mt = 0
    int arow1 = arow0 + 16;                          // mt = 1
    int aqk   = q >> 1;
    // B fragment rows: lanes 0-15 n 0-7 (k lo/hi), 16-31 n 8-15
    int brow_r = col_base + (q >> 1) * 8 + lr;
    int bqk   = q & 1;

    const uint32_t aBase0 = sA + (uint32_t)arow0 * 256u;
    const uint32_t aBase1 = sA + (uint32_t)arow1 * 256u;
    const uint32_t aSw0 = (uint32_t)(arow0 & 7);
    const uint32_t aSw1 = (uint32_t)(arow1 & 7);

    uint32_t aF[2][2][4];   // [buffer][mt][frag]

    // prologue: A fragments for s = 0
    {
        uint32_t kch = (uint32_t)aqk;
        ldsm4(aF[0][0], aBase0 + ((kch ^ aSw0) << 4));
        ldsm4(aF[0][1], aBase1 + ((kch ^ aSw1) << 4));
    }

#pragma unroll
    for (int s = 0; s < 8; s++) {
        const int cur = s & 1, nxt = cur ^ 1;
        uint32_t kchB = (uint32_t)(s * 2 + bqk);
        uint32_t b[4][4];

        {
            int nr0 = brow_r;
            int nr1 = brow_r + 16;
            ldsm4(b[0], sB + (uint32_t)nr0 * 256u + ((kchB ^ (uint32_t)(nr0 & 7)) << 4));
            ldsm4(b[1], sB + (uint32_t)nr1 * 256u + ((kchB ^ (uint32_t)(nr1 & 7)) << 4));
        }
        mma16816(acc[0][0], aF[cur][0], b[0]);
        mma16816(acc[1][0], aF[cur][1], b[0]);
        mma16816(acc[0][1], aF[cur][0], b[0] + 2);
        mma16816(acc[1][1], aF[cur][1], b[0] + 2);
        {
            int nr = brow_r + 32;
            ldsm4(b[2], sB + (uint32_t)nr * 256u + ((kchB ^ (uint32_t)(nr & 7)) << 4));
        }
        mma16816(acc[0][2], aF[cur][0], b[1]);
        mma16816(acc[1][2], aF[cur][1], b[1]);
        mma16816(acc[0][3], aF[cur][0], b[1] + 2);
        mma16816(acc[1][3], aF[cur][1], b[1] + 2);
        {
            int nr = brow_r + 48;
            ldsm4(b[3], sB + (uint32_t)nr * 256u + ((kchB ^ (uint32_t)(nr & 7)) << 4));
        }
        mma16816(acc[0][4], aF[cur][0], b[2]);
        mma16816(acc[1][4], aF[cur][1], b[2]);
        mma16816(acc[0][5], aF[cur][0], b[2] + 2);
        mma16816(acc[1][5], aF[cur][1], b[2] + 2);
        if (s < 7) {
            uint32_t kchA = (uint32_t)((s + 1) * 2 + aqk);
            ldsm4(aF[nxt][0], aBase0 + ((kchA ^ aSw0) << 4));
            ldsm4(aF[nxt][1], aBase1 + ((kchA ^ aSw1) << 4));
        }
        mma16816(acc[0][6], aF[cur][0], b[3]);
        mma16816(acc[1][6], aF[cur][1], b[3]);
        mma16816(acc[0][7], aF[cur][0], b[3] + 2);
        mma16816(acc[1][7], aF[cur][1], b[3] + 2);
    }

    // ---- epilogue: packed f16x2 exp (scale pre-folded) + row sums ----
    // m16n8 accum layout: d0,d1 -> row (lane>>2), d2,d3 -> row (lane>>2)+8.
    // (d0,d1) and (d2,d3) each belong to one row: pack -> ex2.f16x2 -> HADD2.
#pragma unroll
    for (int mt = 0; mt < 2; mt++) {
        __half2 h0 = __floats2half2_rn(0.0f, 0.0f);
        __half2 h1 = __floats2half2_rn(0.0f, 0.0f);
#pragma unroll
        for (int nt = 0; nt < 8; nt++) {
            uint32_t p0 = ex2_f16x2(cvt_f16x2(acc[mt][nt][0], acc[mt][nt][1]));
            uint32_t p1 = ex2_f16x2(cvt_f16x2(acc[mt][nt][2], acc[mt][nt][3]));
            h0 = __hadd2(h0, *(__half2*)&p0);
            h1 = __hadd2(h1, *(__half2*)&p1);
        }
        float s0 = __low2float(h0) + __high2float(h0);
        float s1 = __low2float(h1) + __high2float(h1);
        s0 += __shfl_xor_sync(0xffffffffu, s0, 1);
        s0 += __shfl_xor_sync(0xffffffffu, s0, 2);
        s1 += __shfl_xor_sync(0xffffffffu, s1, 1);
        s1 += __shfl_xor_sync(0xffffffffu, s1, 2);
        if ((lane & 3) == 0) {
            int gr = tile_m * 128 + row_base + mt * 16 + (lane >> 2);
            atomicAdd(&g_rowsum[gr], s0);
            atomicAdd(&g_rowsum[gr + 8], s1);
        }
    }
}

// ---------------------------------------------------------------------------
// Kernel 3: loss = sum_i log(rowsum_i) - (sum diag partials)/T
// 64 blocks x 256 threads: one row per thread; block partial -> atomicAdd.
// ---------------------------------------------------------------------------
__global__ void __launch_bounds__(256) cl_finalize(float* __restrict__ out) {
    __shared__ float sh[256];
    int tid = threadIdx.x;
    int i = blockIdx.x * 256 + tid;              // 0..16383
    float s = __logf(g_rowsum[i]);
    if (i < NROW / 4) s -= 5.0f * g_diag_part[i];
    sh[tid] = s;
    __syncthreads();
    for (int d = 128; d > 0; d >>= 1) {
        if (tid < d) sh[tid] += sh[tid + d];
        __syncthreads();
    }
    if (tid == 0) atomicAdd(out, sh[0]);
}

// ---------------------------------------------------------------------------
extern "C" void kernel_launch(void* const* d_in, const int* in_sizes, int n_in,
                              void* d_out, int out_size) {
    (void)in_sizes; (void)n_in; (void)out_size;
    const float* emb = (const float*)d_in[0];
    float* out = (float*)d_out;

    cudaFuncSetAttribute(cl_gemm, cudaFuncAttributeMaxDynamicSharedMemorySize,
                         65536);

    cl_prep<<<NROW / 4, 128>>>(emb, out);
    cl_gemm<<<dim3(128, 128), 256, 65536>>>();
    cl_finalize<<<NROW / 256, 256>>>(out);
}